// round 3
// baseline (speedup 1.0000x reference)
#include <cuda_runtime.h>

// Shapes (fixed per reference setup_inputs)
#define L_ 12
#define B_ 16
#define H_ 16
#define S_ 577
#define N_ 576      // spatial tokens (S-1)
#define D_ 1024
#define K_ 115      // int(576 * 0.2)

// Scratch: top-k indices per batch (device global — no allocation allowed)
__device__ int g_topk[B_ * K_];

// ---------------------------------------------------------------------------
// Kernel 1: per-batch scores + exact top-K via rank counting.
// One block per batch, 576 threads. Each thread owns one spatial token:
//   score[t] = sum_h attn[b, h, 0, t+1]   (sum ≡ mean for ranking)
// rank[t] = #{ j : score[j] > score[t]  or (==, j<t) }  -> unique ranks,
// exactly matching jax.lax.top_k ordering (desc value, asc index on ties).
// ---------------------------------------------------------------------------
__global__ void topk_kernel(const float* __restrict__ attn) {
    __shared__ float sc[N_];
    const int b = blockIdx.x;
    const int t = threadIdx.x;

    if (t < N_) {
        float s = 0.0f;
        // attn[b, h, 0, t+1] at ((b*H + h)*S + 0)*S + (t+1)
        const float* base = attn + (size_t)b * H_ * S_ * S_ + (t + 1);
        #pragma unroll
        for (int h = 0; h < H_; ++h)
            s += base[(size_t)h * S_ * S_];
        sc[t] = s;
    }
    __syncthreads();

    if (t < N_) {
        const float my = sc[t];
        int rank = 0;
        #pragma unroll 8
        for (int j = 0; j < N_; ++j) {
            const float v = sc[j];
            rank += (v > my) || (v == my && j < t);
        }
        if (rank < K_)
            g_topk[b * K_ + rank] = t;
    }
}

// ---------------------------------------------------------------------------
// Kernel 2: gather selected K/V rows.
// One block per (l, b, k) output row. 256 threads x float4 = 1024 floats.
// Each thread copies one float4 from key_states and one from value_states.
// Reads/writes fully coalesced (4 KB contiguous per row).
// ---------------------------------------------------------------------------
__global__ void gather_kernel(const float* __restrict__ key,
                              const float* __restrict__ val,
                              float* __restrict__ out) {
    const int blk = blockIdx.x;          // l*B*K + b*K + k
    const int k = blk % K_;
    const int b = (blk / K_) % B_;
    const int l = blk / (K_ * B_);

    const int src_s = g_topk[b * K_ + k] + 1;   // +1: skip CLS token

    const size_t src_off = ((((size_t)l * B_ + b) * S_) + src_s) * D_;
    const size_t dst_off = ((((size_t)l * B_ + b) * K_) + k) * (size_t)D_;
    const size_t val_out_base = (size_t)L_ * B_ * K_ * D_;

    const float4* ks = reinterpret_cast<const float4*>(key + src_off);
    const float4* vs = reinterpret_cast<const float4*>(val + src_off);
    float4* ko = reinterpret_cast<float4*>(out + dst_off);
    float4* vo = reinterpret_cast<float4*>(out + val_out_base + dst_off);

    const int t = threadIdx.x;           // 0..255, D/4 = 256 float4 per row
    float4 kv = ks[t];
    float4 vv = vs[t];
    ko[t] = kv;
    vo[t] = vv;
}

extern "C" void kernel_launch(void* const* d_in, const int* in_sizes, int n_in,
                              void* d_out, int out_size) {
    const float* key  = (const float*)d_in[0];  // (12,16,577,1024) f32
    const float* val  = (const float*)d_in[1];  // (12,16,577,1024) f32
    const float* attn = (const float*)d_in[2];  // (16,16,577,577)  f32
    float* out = (float*)d_out;                 // keys then values, each (12,16,115,1024)

    topk_kernel<<<B_, N_>>>(attn);
    gather_kernel<<<L_ * B_ * K_, 256>>>(key, val, out);
}